// round 4
// baseline (speedup 1.0000x reference)
#include <cuda_runtime.h>
#include <cuda_bf16.h>

#define N_NODES 50000
#define N_EDGES 800000
#define D 64
#define N_GRAPHS 1024
#define N_LAYERS 4
#define BN_EPS 1e-5f

// ---------------- scratch (device globals; no allocations allowed) ----------
__device__ __align__(16) float g_u[N_NODES * D];      // (h@W)*dinv[row]
__device__ __align__(16) float g_agg[N_NODES * D];    // accumulator (init = u)
__device__ __align__(16) float g_y[N_NODES * D];      // pre-BN activations
__device__ __align__(16) float g_dinv[N_NODES];       // deg -> rsqrt(deg)
__device__ __align__(16) float g_pooled[N_GRAPHS * D];
__device__ __align__(16) float g_stats[2 * D];        // [sum, sumsq]
__device__ __align__(16) float g_scale[D];
__device__ __align__(16) float g_shift[D];
__device__ unsigned int g_cnt;                         // last-block ticket

// vectorized global reduction (fp32 add, no return) — sm_90+
__device__ __forceinline__ void red_add_v4(float* addr, float4 v) {
    asm volatile("red.global.add.v4.f32 [%0], {%1,%2,%3,%4};"
                 :: "l"(addr), "f"(v.x), "f"(v.y), "f"(v.z), "f"(v.w)
                 : "memory");
}

// ---------------- kernels ---------------------------------------------------

// init: deg=1 (self loop), pooled=0, ticket=0
__global__ void k_init() {
    int i = blockIdx.x * blockDim.x + threadIdx.x;
    if (i < N_NODES) g_dinv[i] = 1.0f;
    if (i < N_GRAPHS * D) g_pooled[i] = 0.0f;
    if (i == 0) g_cnt = 0u;
}

// degree accumulation over edge dst
__global__ void k_deg(const int* __restrict__ ei) {
    int e = blockIdx.x * blockDim.x + threadIdx.x;
    if (e < N_EDGES) atomicAdd(&g_dinv[ei[N_EDGES + e]], 1.0f);
}

__global__ void k_rsqrt() {
    int i = blockIdx.x * blockDim.x + threadIdx.x;
    if (i < N_NODES) g_dinv[i] = rsqrtf(g_dinv[i]);
}

// GEMM: u[r][c] = (sum_k hin[r][k]*W[k][c]) * dinv[r]; agg := u (self-loop).
// hin == nullptr => input is relu(g_y * g_scale + g_shift) (fused BN+ReLU).
// 256 threads, tile 64 rows x 64 cols, per-thread 4x4 register tile,
// register-double-buffered k-loop to hide LDS latency.
__global__ void __launch_bounds__(256, 3) k_gemm(const float* __restrict__ hin_arg,
                                                 const float* __restrict__ W) {
    __shared__ float Wsh[64 * 64];
    __shared__ float hsT[64 * 68];   // [k][r], pad 68
    __shared__ float ssc[64], ssh[64];

    const int tid = threadIdx.x;
    const int tx = tid & 15;         // c0 = tx*4
    const int ty = tid >> 4;         // r0 = ty*4
    const int row0 = blockIdx.x * 64;

    // zero BN stats for this layer (block 0, pre-sync; kernels serialize)
    if (blockIdx.x == 0 && tid < 2 * D) g_stats[tid] = 0.0f;
    if (tid < 64) { ssc[tid] = g_scale[tid]; ssh[tid] = g_shift[tid]; }

    for (int i = tid; i < 64 * 64; i += 256) Wsh[i] = W[i];

    if (hin_arg) {
        #pragma unroll
        for (int i = tid; i < 64 * 64; i += 256) {
            int r = i >> 6, k = i & 63;
            int gr = row0 + r;
            hsT[k * 68 + r] = (gr < N_NODES) ? hin_arg[gr * D + k] : 0.0f;
        }
        __syncthreads();
    } else {
        __syncthreads();   // ssc/ssh visible
        #pragma unroll
        for (int i = tid; i < 64 * 64; i += 256) {
            int r = i >> 6, k = i & 63;
            int gr = row0 + r;
            float v = 0.0f;
            if (gr < N_NODES)
                v = fmaxf(g_y[gr * D + k] * ssc[k] + ssh[k], 0.0f);
            hsT[k * 68 + r] = v;
        }
        __syncthreads();
    }

    float acc[4][4];
    #pragma unroll
    for (int a = 0; a < 4; a++)
        #pragma unroll
        for (int b = 0; b < 4; b++) acc[a][b] = 0.0f;

    const int r0 = ty * 4, c0 = tx * 4;

    // register double-buffered k-loop (prefetch wraps to 0 on last iter: defined,
    // unpredicated LDS in the unrolled body)
    float4 hv = *(const float4*)&hsT[r0];
    float4 wv = *(const float4*)&Wsh[c0];
    #pragma unroll
    for (int k = 0; k < 64; k++) {
        const int kn = (k + 1) & 63;
        float4 hn = *(const float4*)&hsT[kn * 68 + r0];
        float4 wn = *(const float4*)&Wsh[kn * 64 + c0];
        acc[0][0] += hv.x * wv.x; acc[0][1] += hv.x * wv.y; acc[0][2] += hv.x * wv.z; acc[0][3] += hv.x * wv.w;
        acc[1][0] += hv.y * wv.x; acc[1][1] += hv.y * wv.y; acc[1][2] += hv.y * wv.z; acc[1][3] += hv.y * wv.w;
        acc[2][0] += hv.z * wv.x; acc[2][1] += hv.z * wv.y; acc[2][2] += hv.z * wv.z; acc[2][3] += hv.z * wv.w;
        acc[3][0] += hv.w * wv.x; acc[3][1] += hv.w * wv.y; acc[3][2] += hv.w * wv.z; acc[3][3] += hv.w * wv.w;
        hv = hn; wv = wn;
    }

    #pragma unroll
    for (int a = 0; a < 4; a++) {
        int r = row0 + r0 + a;
        if (r < N_NODES) {
            float d = g_dinv[r];
            float4 v = make_float4(acc[a][0] * d, acc[a][1] * d, acc[a][2] * d, acc[a][3] * d);
            *(float4*)&g_u[r * D + c0]   = v;
            *(float4*)&g_agg[r * D + c0] = v;
        }
    }
}

// edge scatter: agg[dst] += u[src]  (8 threads per edge, 2x float4 each)
__global__ void k_edge(const int* __restrict__ ei) {
    long long idx = (long long)blockIdx.x * blockDim.x + threadIdx.x;
    if (idx >= (long long)N_EDGES * 8) return;
    int e = (int)(idx >> 3);
    int c = (int)(idx & 7) << 3;      // 8 floats per thread
    int s = __ldg(&ei[e]);
    int d = __ldg(&ei[N_EDGES + e]);
    const float4* up = (const float4*)&g_u[s * D + c];
    float4 v0 = up[0];
    float4 v1 = up[1];
    red_add_v4(&g_agg[d * D + c], v0);
    red_add_v4(&g_agg[d * D + c + 4], v1);
}

// y = dinv[r]*agg + b[c]; accumulate column stats; LAST block finalizes
// scale/shift (fused finalize) via ticket + threadfence.
__global__ void k_stats(const float* __restrict__ b,
                        const float* __restrict__ gamma,
                        const float* __restrict__ beta) {
    __shared__ float red1[4][64];
    __shared__ float red2[4][64];
    __shared__ bool isLast;
    const int c = threadIdx.x;           // 0..63
    const int ty = threadIdx.y;          // 0..3
    const int tid = ty * 64 + c;
    const float bc = b[c];
    float s1 = 0.0f, s2 = 0.0f;
    for (int r = blockIdx.x * 4 + ty; r < N_NODES; r += gridDim.x * 4) {
        float y = g_dinv[r] * g_agg[r * D + c] + bc;
        g_y[r * D + c] = y;
        s1 += y;
        s2 += y * y;
    }
    red1[ty][c] = s1;
    red2[ty][c] = s2;
    __syncthreads();
    if (ty == 0) {
        float t1 = red1[0][c] + red1[1][c] + red1[2][c] + red1[3][c];
        float t2 = red2[0][c] + red2[1][c] + red2[2][c] + red2[3][c];
        atomicAdd(&g_stats[c], t1);
        atomicAdd(&g_stats[D + c], t2);
    }
    __threadfence();
    if (tid == 0) {
        unsigned t = atomicAdd(&g_cnt, 1u);
        isLast = (t == gridDim.x - 1);
    }
    __syncthreads();
    if (isLast) {
        if (ty == 0) {
            float mean = g_stats[c] * (1.0f / N_NODES);
            float var  = g_stats[D + c] * (1.0f / N_NODES) - mean * mean;
            float sc = gamma[c] * rsqrtf(var + BN_EPS);
            g_scale[c] = sc;
            g_shift[c] = beta[c] - mean * sc;
        }
        if (tid == 0) g_cnt = 0u;   // rearm ticket for next layer
    }
}

// final layer: h = relu(y*scale+shift); pooled[batch[n]] += h  (fused)
__global__ void k_poolfused(const int* __restrict__ batch) {
    long long idx = (long long)blockIdx.x * blockDim.x + threadIdx.x;
    if (idx >= (long long)N_NODES * 16) return;
    int n = (int)(idx >> 4);
    int c = (int)(idx & 15) << 2;
    int g = __ldg(&batch[n]);
    float4 y  = *(const float4*)&g_y[n * D + c];
    float4 sc = *(const float4*)&g_scale[c];
    float4 sh = *(const float4*)&g_shift[c];
    float4 h;
    h.x = fmaxf(y.x * sc.x + sh.x, 0.0f);
    h.y = fmaxf(y.y * sc.y + sh.y, 0.0f);
    h.z = fmaxf(y.z * sc.z + sh.z, 0.0f);
    h.w = fmaxf(y.w * sc.w + sh.w, 0.0f);
    red_add_v4(&g_pooled[g * D + c], h);
}

// tiny MLP head: one block per graph, 64 threads
__global__ void k_mlp(const float* __restrict__ w1, const float* __restrict__ b1,
                      const float* __restrict__ w2, const float* __restrict__ b2,
                      const float* __restrict__ w3, const float* __restrict__ b3,
                      float* __restrict__ out) {
    __shared__ float pr[64], z1[64], z2[64], red[64];
    const int g = blockIdx.x;
    const int c = threadIdx.x;
    pr[c] = g_pooled[g * D + c];
    __syncthreads();
    float a = b1[c];
    #pragma unroll 8
    for (int k = 0; k < 64; k++) a += pr[k] * w1[k * D + c];
    z1[c] = fmaxf(a, 0.0f);
    __syncthreads();
    a = b2[c];
    #pragma unroll 8
    for (int k = 0; k < 64; k++) a += z1[k] * w2[k * D + c];
    z2[c] = fmaxf(a, 0.0f);
    __syncthreads();
    red[c] = z2[c] * w3[c];
    __syncthreads();
    if (c == 0) {
        float s = b3[0];
        #pragma unroll
        for (int k = 0; k < 64; k++) s += red[k];
        out[g] = s;
    }
}

// ---------------- launch -----------------------------------------------------
extern "C" void kernel_launch(void* const* d_in, const int* in_sizes, int n_in,
                              void* d_out, int out_size) {
    const float* x     = (const float*)d_in[0];
    const int*   ei    = (const int*)d_in[1];
    const int*   batch = (const int*)d_in[2];
    const float* Ws    = (const float*)d_in[3];
    const float* bs    = (const float*)d_in[4];
    const float* gamma = (const float*)d_in[5];
    const float* beta  = (const float*)d_in[6];
    const float* w1    = (const float*)d_in[7];
    const float* b1    = (const float*)d_in[8];
    const float* w2    = (const float*)d_in[9];
    const float* b2    = (const float*)d_in[10];
    const float* w3    = (const float*)d_in[11];
    const float* b3    = (const float*)d_in[12];
    float* out = (float*)d_out;

    k_init<<<(N_GRAPHS * D + 255) / 256, 256>>>();
    k_deg<<<(N_EDGES + 255) / 256, 256>>>(ei);
    k_rsqrt<<<(N_NODES + 255) / 256, 256>>>();

    for (int l = 0; l < N_LAYERS; l++) {
        const float* hin = (l == 0) ? x : nullptr;  // nullptr => fused BN+ReLU from g_y
        k_gemm<<<(N_NODES + 63) / 64, 256>>>(hin, Ws + l * D * D);
        k_edge<<<(N_EDGES * 8 + 255) / 256, 256>>>(ei);
        k_stats<<<256, dim3(64, 4)>>>(bs + l * D, gamma + l * D, beta + l * D);
    }

    k_poolfused<<<(N_NODES * 16) / 256, 256>>>(batch);
    k_mlp<<<N_GRAPHS, 64>>>(w1, b1, w2, b2, w3, b3, out);
}

// round 5
// speedup vs baseline: 1.7772x; 1.7772x over previous
#include <cuda_runtime.h>
#include <cuda_bf16.h>

#define N_NODES 50000
#define N_EDGES 800000
#define D 64
#define N_GRAPHS 1024
#define N_LAYERS 4
#define BN_EPS 1e-5f

#define SCAN_BLK 512
#define SCAN_NBLK ((N_NODES + SCAN_BLK - 1) / SCAN_BLK)   // 98
#define GATHER_GRID 1184                                  // 148*8 blocks

// ---------------- scratch (device globals; no allocations allowed) ----------
__device__ __align__(16) float g_u[N_NODES * D];      // (h@W)*dinv[row]
__device__ __align__(16) float g_y[N_NODES * D];      // pre-BN activations
__device__ __align__(16) float g_dinv[N_NODES];       // rsqrt(deg)
__device__ __align__(16) float g_pooled[N_GRAPHS * D];
__device__ __align__(16) float g_stats[2 * D];        // [sum, sumsq]
__device__ __align__(16) float g_scale[D];
__device__ __align__(16) float g_shift[D];
__device__ int   g_count[N_NODES];                    // in-degree histogram
__device__ int   g_rowtmp[N_NODES];                   // local exclusive scan
__device__ int   g_rowstart[N_NODES + 1];             // CSR row offsets
__device__ int   g_cursor[N_NODES];                   // fill cursors
__device__ int   g_csrc[N_EDGES];                     // CSR src lists (by dst)
__device__ int   g_bsum[SCAN_NBLK + 2];               // scan block sums
__device__ unsigned int g_cnt;                         // last-block ticket

// vectorized global reduction (fp32 add, no return) — sm_90+
__device__ __forceinline__ void red_add_v4(float* addr, float4 v) {
    asm volatile("red.global.add.v4.f32 [%0], {%1,%2,%3,%4};"
                 :: "l"(addr), "f"(v.x), "f"(v.y), "f"(v.z), "f"(v.w)
                 : "memory");
}

// ---------------- setup kernels ---------------------------------------------

__global__ void k_init() {
    int i = blockIdx.x * blockDim.x + threadIdx.x;
    if (i < N_NODES) g_count[i] = 0;
    if (i < N_GRAPHS * D) g_pooled[i] = 0.0f;
    if (i == 0) g_cnt = 0u;
}

__global__ void k_count(const int* __restrict__ ei) {
    int e = blockIdx.x * blockDim.x + threadIdx.x;
    if (e < N_EDGES) atomicAdd(&g_count[ei[N_EDGES + e]], 1);
}

// block-local exclusive scan + block sums
__global__ void k_scan1() {
    __shared__ int sm[SCAN_BLK];
    int i = blockIdx.x * SCAN_BLK + threadIdx.x;
    int v = (i < N_NODES) ? g_count[i] : 0;
    sm[threadIdx.x] = v;
    __syncthreads();
    for (int off = 1; off < SCAN_BLK; off <<= 1) {
        int t = (threadIdx.x >= off) ? sm[threadIdx.x - off] : 0;
        __syncthreads();
        sm[threadIdx.x] += t;
        __syncthreads();
    }
    if (i < N_NODES) g_rowtmp[i] = sm[threadIdx.x] - v;  // exclusive
    if (threadIdx.x == SCAN_BLK - 1) g_bsum[blockIdx.x] = sm[SCAN_BLK - 1];
}

// serial scan of 98 block sums (trivial)
__global__ void k_scan2() {
    if (threadIdx.x == 0) {
        int acc = 0;
        for (int b = 0; b < SCAN_NBLK; b++) { int t = g_bsum[b]; g_bsum[b] = acc; acc += t; }
    }
}

// finalize rowstart/cursor + dinv
__global__ void k_scan3() {
    int i = blockIdx.x * blockDim.x + threadIdx.x;
    if (i < N_NODES) {
        int rs = g_rowtmp[i] + g_bsum[i >> 9];   // 512 = 2^9
        g_rowstart[i] = rs;
        g_cursor[i]   = rs;
        g_dinv[i] = rsqrtf((float)g_count[i] + 1.0f);
    }
    if (i == 0) g_rowstart[N_NODES] = N_EDGES;
}

__global__ void k_fill(const int* __restrict__ ei) {
    int e = blockIdx.x * blockDim.x + threadIdx.x;
    if (e < N_EDGES) {
        int s = ei[e];
        int d = ei[N_EDGES + e];
        int pos = atomicAdd(&g_cursor[d], 1);
        g_csrc[pos] = s;
    }
}

// ---------------- per-layer kernels ------------------------------------------

// GEMM: u[r][c] = (sum_k hin[r][k]*W[k][c]) * dinv[r].
// hin == nullptr => input is relu(g_y * g_scale + g_shift) (fused BN+ReLU).
__global__ void __launch_bounds__(256, 3) k_gemm(const float* __restrict__ hin_arg,
                                                 const float* __restrict__ W) {
    __shared__ float Wsh[64 * 64];
    __shared__ float hsT[64 * 68];
    __shared__ float ssc[64], ssh[64];

    const int tid = threadIdx.x;
    const int tx = tid & 15;
    const int ty = tid >> 4;
    const int row0 = blockIdx.x * 64;

    if (blockIdx.x == 0 && tid < 2 * D) g_stats[tid] = 0.0f;  // pre-layer zero
    if (tid < 64) { ssc[tid] = g_scale[tid]; ssh[tid] = g_shift[tid]; }

    for (int i = tid; i < 64 * 64; i += 256) Wsh[i] = W[i];

    if (hin_arg) {
        #pragma unroll
        for (int i = tid; i < 64 * 64; i += 256) {
            int r = i >> 6, k = i & 63;
            int gr = row0 + r;
            hsT[k * 68 + r] = (gr < N_NODES) ? hin_arg[gr * D + k] : 0.0f;
        }
        __syncthreads();
    } else {
        __syncthreads();
        #pragma unroll
        for (int i = tid; i < 64 * 64; i += 256) {
            int r = i >> 6, k = i & 63;
            int gr = row0 + r;
            float v = 0.0f;
            if (gr < N_NODES)
                v = fmaxf(g_y[gr * D + k] * ssc[k] + ssh[k], 0.0f);
            hsT[k * 68 + r] = v;
        }
        __syncthreads();
    }

    float acc[4][4];
    #pragma unroll
    for (int a = 0; a < 4; a++)
        #pragma unroll
        for (int b = 0; b < 4; b++) acc[a][b] = 0.0f;

    const int r0 = ty * 4, c0 = tx * 4;

    float4 hv = *(const float4*)&hsT[r0];
    float4 wv = *(const float4*)&Wsh[c0];
    #pragma unroll
    for (int k = 0; k < 64; k++) {
        const int kn = (k + 1) & 63;
        float4 hn = *(const float4*)&hsT[kn * 68 + r0];
        float4 wn = *(const float4*)&Wsh[kn * 64 + c0];
        acc[0][0] += hv.x * wv.x; acc[0][1] += hv.x * wv.y; acc[0][2] += hv.x * wv.z; acc[0][3] += hv.x * wv.w;
        acc[1][0] += hv.y * wv.x; acc[1][1] += hv.y * wv.y; acc[1][2] += hv.y * wv.z; acc[1][3] += hv.y * wv.w;
        acc[2][0] += hv.z * wv.x; acc[2][1] += hv.z * wv.y; acc[2][2] += hv.z * wv.z; acc[2][3] += hv.z * wv.w;
        acc[3][0] += hv.w * wv.x; acc[3][1] += hv.w * wv.y; acc[3][2] += hv.w * wv.z; acc[3][3] += hv.w * wv.w;
        hv = hn; wv = wn;
    }

    #pragma unroll
    for (int a = 0; a < 4; a++) {
        int r = row0 + r0 + a;
        if (r < N_NODES) {
            float d = g_dinv[r];
            *(float4*)&g_u[r * D + c0] =
                make_float4(acc[a][0] * d, acc[a][1] * d, acc[a][2] * d, acc[a][3] * d);
        }
    }
}

// CSR gather + y + BN stats + ticket finalize.  One warp per node (grid-stride).
// Half-warps process alternating edges; lanes cover 64 cols as 16 x float4.
__global__ void __launch_bounds__(256) k_gather(const float* __restrict__ b,
                                                const float* __restrict__ gamma,
                                                const float* __restrict__ beta) {
    __shared__ float sm1[8 * 64];
    __shared__ float sm2[8 * 64];
    __shared__ bool isLast;

    const int tid = threadIdx.x;
    const int w = tid >> 5;
    const int lane = tid & 31;
    const int half = lane >> 4;
    const int cl = (lane & 15) << 2;

    float s1x = 0.f, s1y = 0.f, s1z = 0.f, s1w = 0.f;
    float s2x = 0.f, s2y = 0.f, s2z = 0.f, s2w = 0.f;
    const float4 bv = *(const float4*)&b[cl];

    for (int n = blockIdx.x * 8 + w; n < N_NODES; n += GATHER_GRID * 8) {
        const int beg = g_rowstart[n];
        const int end = g_rowstart[n + 1];
        float4 acc = make_float4(0.f, 0.f, 0.f, 0.f);
        for (int j = beg + half; j < end; j += 2) {
            int s = __ldg(&g_csrc[j]);
            float4 v = *(const float4*)&g_u[s * D + cl];
            acc.x += v.x; acc.y += v.y; acc.z += v.z; acc.w += v.w;
        }
        acc.x += __shfl_xor_sync(0xffffffffu, acc.x, 16);
        acc.y += __shfl_xor_sync(0xffffffffu, acc.y, 16);
        acc.z += __shfl_xor_sync(0xffffffffu, acc.z, 16);
        acc.w += __shfl_xor_sync(0xffffffffu, acc.w, 16);
        if (half == 0) {
            float4 us = *(const float4*)&g_u[n * D + cl];
            float dv = g_dinv[n];
            float4 y;
            y.x = dv * (acc.x + us.x) + bv.x;
            y.y = dv * (acc.y + us.y) + bv.y;
            y.z = dv * (acc.z + us.z) + bv.z;
            y.w = dv * (acc.w + us.w) + bv.w;
            *(float4*)&g_y[n * D + cl] = y;
            s1x += y.x; s1y += y.y; s1z += y.z; s1w += y.w;
            s2x += y.x * y.x; s2y += y.y * y.y; s2z += y.z * y.z; s2w += y.w * y.w;
        }
    }

    if (half == 0) {
        sm1[w * 64 + cl + 0] = s1x; sm1[w * 64 + cl + 1] = s1y;
        sm1[w * 64 + cl + 2] = s1z; sm1[w * 64 + cl + 3] = s1w;
        sm2[w * 64 + cl + 0] = s2x; sm2[w * 64 + cl + 1] = s2y;
        sm2[w * 64 + cl + 2] = s2z; sm2[w * 64 + cl + 3] = s2w;
    }
    __syncthreads();
    if (tid < 64) {
        float t1 = 0.f, t2 = 0.f;
        #pragma unroll
        for (int ww = 0; ww < 8; ww++) { t1 += sm1[ww * 64 + tid]; t2 += sm2[ww * 64 + tid]; }
        atomicAdd(&g_stats[tid], t1);       // result unused -> RED
        atomicAdd(&g_stats[D + tid], t2);
    }
    __threadfence();
    if (tid == 0) isLast = (atomicAdd(&g_cnt, 1u) == (unsigned)(gridDim.x - 1));
    __syncthreads();
    if (isLast) {
        if (tid < 64) {
            float mean = g_stats[tid] * (1.0f / N_NODES);
            float var  = g_stats[D + tid] * (1.0f / N_NODES) - mean * mean;
            float sc = gamma[tid] * rsqrtf(var + BN_EPS);
            g_scale[tid] = sc;
            g_shift[tid] = beta[tid] - mean * sc;
        }
        if (tid == 0) g_cnt = 0u;   // rearm
    }
}

// final layer: h = relu(y*scale+shift); pooled[batch[n]] += h  (fused)
__global__ void k_poolfused(const int* __restrict__ batch) {
    long long idx = (long long)blockIdx.x * blockDim.x + threadIdx.x;
    if (idx >= (long long)N_NODES * 16) return;
    int n = (int)(idx >> 4);
    int c = (int)(idx & 15) << 2;
    int g = __ldg(&batch[n]);
    float4 y  = *(const float4*)&g_y[n * D + c];
    float4 sc = *(const float4*)&g_scale[c];
    float4 sh = *(const float4*)&g_shift[c];
    float4 h;
    h.x = fmaxf(y.x * sc.x + sh.x, 0.0f);
    h.y = fmaxf(y.y * sc.y + sh.y, 0.0f);
    h.z = fmaxf(y.z * sc.z + sh.z, 0.0f);
    h.w = fmaxf(y.w * sc.w + sh.w, 0.0f);
    red_add_v4(&g_pooled[g * D + c], h);
}

// tiny MLP head: one block per graph, 64 threads
__global__ void k_mlp(const float* __restrict__ w1, const float* __restrict__ b1,
                      const float* __restrict__ w2, const float* __restrict__ b2,
                      const float* __restrict__ w3, const float* __restrict__ b3,
                      float* __restrict__ out) {
    __shared__ float pr[64], z1[64], z2[64], red[64];
    const int g = blockIdx.x;
    const int c = threadIdx.x;
    pr[c] = g_pooled[g * D + c];
    __syncthreads();
    float a = b1[c];
    #pragma unroll 8
    for (int k = 0; k < 64; k++) a += pr[k] * w1[k * D + c];
    z1[c] = fmaxf(a, 0.0f);
    __syncthreads();
    a = b2[c];
    #pragma unroll 8
    for (int k = 0; k < 64; k++) a += z1[k] * w2[k * D + c];
    z2[c] = fmaxf(a, 0.0f);
    __syncthreads();
    red[c] = z2[c] * w3[c];
    __syncthreads();
    if (c == 0) {
        float s = b3[0];
        #pragma unroll
        for (int k = 0; k < 64; k++) s += red[k];
        out[g] = s;
    }
}

// ---------------- launch -----------------------------------------------------
extern "C" void kernel_launch(void* const* d_in, const int* in_sizes, int n_in,
                              void* d_out, int out_size) {
    const float* x     = (const float*)d_in[0];
    const int*   ei    = (const int*)d_in[1];
    const int*   batch = (const int*)d_in[2];
    const float* Ws    = (const float*)d_in[3];
    const float* bs    = (const float*)d_in[4];
    const float* gamma = (const float*)d_in[5];
    const float* beta  = (const float*)d_in[6];
    const float* w1    = (const float*)d_in[7];
    const float* b1    = (const float*)d_in[8];
    const float* w2    = (const float*)d_in[9];
    const float* b2    = (const float*)d_in[10];
    const float* w3    = (const float*)d_in[11];
    const float* b3    = (const float*)d_in[12];
    float* out = (float*)d_out;

    // CSR build (once per launch)
    k_init<<<(N_GRAPHS * D + 255) / 256, 256>>>();
    k_count<<<(N_EDGES + 255) / 256, 256>>>(ei);
    k_scan1<<<SCAN_NBLK, SCAN_BLK>>>();
    k_scan2<<<1, 32>>>();
    k_scan3<<<(N_NODES + 255) / 256, 256>>>();
    k_fill<<<(N_EDGES + 255) / 256, 256>>>(ei);

    for (int l = 0; l < N_LAYERS; l++) {
        const float* hin = (l == 0) ? x : nullptr;  // nullptr => fused BN+ReLU from g_y
        k_gemm<<<(N_NODES + 63) / 64, 256>>>(hin, Ws + l * D * D);
        k_gather<<<GATHER_GRID, 256>>>(bs + l * D, gamma + l * D, beta + l * D);
    }

    k_poolfused<<<(N_NODES * 16) / 256, 256>>>(batch);
    k_mlp<<<N_GRAPHS, 64>>>(w1, b1, w2, b2, w3, b3, out);
}